// round 5
// baseline (speedup 1.0000x reference)
#include <cuda_runtime.h>

// PointerNet_30949534335591 — FINAL (terminal kernel; floor confirmed, R5)
//
// Mathematical identity (exact, rel_err = 0.0 across all rounds): the decoder
// computes logits of shape [B, 1] and argmaxes over the length-1 axis ->
// identically 0 for every batch element and step, independent of all LSTM
// state. The output is a constant zero [B, S] int32 tensor; the entire
// encoder/decoder LSTM stack (~110 GFLOP) is dead code w.r.t. the output.
//
// Performance model (validated R1-R4):
//   - d_out is poisoned to 0xAA before timing -> all 512 KB must be written
//     on every graph replay. Minimum correct write set.
//   - 512 KB of stores = ~0.06 us of memory time; measured 5.0-5.9 us ->
//     >98% is fixed per-replay overhead (host cudaGraphLaunch + node
//     launch-to-complete latency). Not addressable from the .cu.
//   - Node-type samples: kernel node 5.79 us; memset node 5.06 / 5.09 /
//     5.89 us. Within-session noise +/-0.05 us; cross-session ~+/-0.8 us.
//     Memset node never slower than kernel node -> keep it.
//   - Alternatives rejected: CE memcpy-from-zero-buffer (extra 512 KB read +
//     CE latency), multi-node graphs (per-node overhead dominates), smaller
//     writes (impossible: poisoned output).
//
// Minimal correct graph: ONE memset node writing the minimum byte count.
// Source changes beyond this point would only measure session variance.

extern "C" void kernel_launch(void* const* d_in, const int* in_sizes, int n_in,
                              void* d_out, int out_size) {
    (void)d_in; (void)in_sizes; (void)n_in;
    // Captured as a single CUDA-graph memset node: zero B*S int32 elements.
    cudaMemsetAsync(d_out, 0, (size_t)out_size * sizeof(int), 0);
}

// round 6
// speedup vs baseline: 1.2115x; 1.2115x over previous
#include <cuda_runtime.h>
#include <cstdint>

// PointerNet_30949534335591 — R6: kernel-node re-sample experiment
//
// Output identity unchanged (exact, rel_err = 0.0 all rounds): argmax over a
// length-1 axis -> constant zero [B, S] int32 tensor; all LSTM work is dead
// code. Must write all 512 KB per replay (output poisoned to 0xAA).
//
// Why a kernel node again: identical memset-node source measured 5.06, 5.09,
// 5.89, 6.05 us across sessions — cross-session drift (~1 us) swamps the
// single R1 kernel-node sample (5.79) behind the "memset node is cheaper"
// conclusion. This round re-samples kernel-node cost in the current regime:
//   ~= memset (5.5-6.5)  -> node type irrelevant, true floor ~5 us, terminal
//   <  5.3               -> kernel node actually cheaper here, keep it
//
// GPU-side cost minimized so the sample isolates node overhead: one wave
// (64 CTAs x 256 threads), 2 independent int4 stores per thread (MLP=2),
// no predication on the exact-size path, no barriers.

__global__ void __launch_bounds__(256, 1)
pointer_net_zero2(int4* __restrict__ out) {
    // 64 blocks * 256 threads * 2 int4 = 32768 int4 = 131072 int32 = 512 KB
    int idx = (blockIdx.x * 256 + threadIdx.x) * 2;
    const int4 z = make_int4(0, 0, 0, 0);
    out[idx]     = z;
    out[idx + 1] = z;
}

__global__ void pointer_net_zero_generic(int* __restrict__ out, int n) {
    int idx = blockIdx.x * blockDim.x + threadIdx.x;
    if (idx < n) out[idx] = 0;
}

extern "C" void kernel_launch(void* const* d_in, const int* in_sizes, int n_in,
                              void* d_out, int out_size) {
    (void)d_in; (void)in_sizes; (void)n_in;

    uintptr_t p = reinterpret_cast<uintptr_t>(d_out);
    if (out_size == 131072 && (p & 0xF) == 0) {
        // Exact expected shape: B*S = 256*512. One wave, unpredicated stores.
        pointer_net_zero2<<<64, 256>>>(reinterpret_cast<int4*>(d_out));
    } else {
        int threads = 256;
        int blocks = (out_size + threads - 1) / threads;
        pointer_net_zero_generic<<<blocks, threads>>>(
            reinterpret_cast<int*>(d_out), out_size);
    }
}